// round 2
// baseline (speedup 1.0000x reference)
#include <cuda_runtime.h>
#include <math.h>

#define H 256
#define MAXE 500000
#define MAXG 256
#define FRONTIER_BONUS 0.5f
#define LN_EPS 1e-5f
#define F32_EPS 1.1920929e-07f
#define NBLK_P1 1184

// ---------------- device scratch (no allocation allowed) ----------------
__device__ float g_w_att[H];          // att_vec @ W_edge
__device__ float g_w_q[H];            // att_vec @ W_query
__device__ float g_qatt[MAXG];        // question_tokens[g] . g_w_q
__device__ float g_S[MAXG * H];       // segment sums of edge_tokens
__device__ int   g_maxenc[MAXG];      // orderable-int encoded segment max of att_raw
__device__ float g_sumexp[MAXG];      // segment sum of masked exp
__device__ int   g_cnt[MAXG];         // edges per graph
__device__ float g_att[MAXE];         // att_raw per edge

// float <-> orderable signed int (monotonic, for atomicMax)
__device__ __forceinline__ int f2o(float f) {
    int i = __float_as_int(f);
    return i >= 0 ? i : (i ^ 0x7FFFFFFF);
}
__device__ __forceinline__ float o2f(int i) {
    return __int_as_float(i >= 0 ? i : (i ^ 0x7FFFFFFF));
}

// ---------------- init ----------------
__global__ void init_k(int G) {
    int i = blockIdx.x * blockDim.x + threadIdx.x;
    int n = G * H;
    for (int j = i; j < n; j += gridDim.x * blockDim.x) g_S[j] = 0.f;
    if (i < G) {
        g_maxenc[i] = f2o(-INFINITY);
        g_sumexp[i] = 0.f;
        g_cnt[i] = 0;
    }
}

// ---------------- precompute w_att, w_q ----------------
__global__ void prew_k(const float* __restrict__ W_edge,
                       const float* __restrict__ W_query,
                       const float* __restrict__ att_vec) {
    int j = threadIdx.x;
    const float* W = (blockIdx.x == 0) ? W_edge : W_query;
    float s = 0.f;
    #pragma unroll 8
    for (int i = 0; i < H; i++) s += att_vec[i] * W[i * H + j];
    if (blockIdx.x == 0) g_w_att[j] = s; else g_w_q[j] = s;
}

// ---------------- qatt[g] = question_tokens[g] . w_q ----------------
__global__ void qatt_k(const float* __restrict__ qtok, int G) {
    int w = threadIdx.x >> 5, l = threadIdx.x & 31;
    int g = blockIdx.x * 8 + w;
    if (g >= G) return;
    float s = 0.f;
    #pragma unroll
    for (int k = 0; k < 8; k++) {
        int j = l + 32 * k;
        s += qtok[(size_t)g * H + j] * g_w_q[j];
    }
    #pragma unroll
    for (int sh = 16; sh; sh >>= 1) s += __shfl_xor_sync(0xFFFFFFFFu, s, sh);
    if (l == 0) g_qatt[g] = s;
}

// ---------------- main streaming pass over edge_tokens ----------------
// warp-per-edge, 8 warps/block, contiguous chunk per block. Sorted edge_batch
// -> per-warp run accumulation of segment sums / max / count, rare atomic flush.
__global__ void __launch_bounds__(256) pass1_k(const float* __restrict__ x,
                        const int* __restrict__ batch,
                        const int* __restrict__ sel,
                        int E) {
    int chunk = (E + NBLK_P1 - 1) / NBLK_P1;
    int lo = blockIdx.x * chunk;
    int hi = min(E, lo + chunk);
    int w = threadIdx.x >> 5, l = threadIdx.x & 31;

    const float4* wav = (const float4*)g_w_att;
    float4 wa0 = wav[l];       // cols 4l..4l+3
    float4 wa1 = wav[32 + l];  // cols 128+4l..128+4l+3

    float4 a0 = make_float4(0.f, 0.f, 0.f, 0.f);
    float4 a1 = make_float4(0.f, 0.f, 0.f, 0.f);
    int cur = -1, rcnt = 0;
    float rmax = -INFINITY;

    for (int e = lo + w; e < hi; e += 8) {
        int g = __ldg(batch + e);
        if (g != cur) {
            if (cur >= 0) {
                float* Sp = &g_S[cur * H];
                atomicAdd(Sp + 4 * l + 0, a0.x);
                atomicAdd(Sp + 4 * l + 1, a0.y);
                atomicAdd(Sp + 4 * l + 2, a0.z);
                atomicAdd(Sp + 4 * l + 3, a0.w);
                atomicAdd(Sp + 128 + 4 * l + 0, a1.x);
                atomicAdd(Sp + 128 + 4 * l + 1, a1.y);
                atomicAdd(Sp + 128 + 4 * l + 2, a1.z);
                atomicAdd(Sp + 128 + 4 * l + 3, a1.w);
                if (l == 0) {
                    atomicMax(&g_maxenc[cur], f2o(rmax));
                    atomicAdd(&g_cnt[cur], rcnt);
                }
            }
            a0 = make_float4(0.f, 0.f, 0.f, 0.f);
            a1 = make_float4(0.f, 0.f, 0.f, 0.f);
            rmax = -INFINITY; rcnt = 0; cur = g;
        }
        const float4* row = (const float4*)(x + (size_t)e * H);
        float4 x0 = row[l];
        float4 x1 = row[32 + l];
        a0.x += x0.x; a0.y += x0.y; a0.z += x0.z; a0.w += x0.w;
        a1.x += x1.x; a1.y += x1.y; a1.z += x1.z; a1.w += x1.w;
        float d = x0.x * wa0.x + x0.y * wa0.y + x0.z * wa0.z + x0.w * wa0.w
                + x1.x * wa1.x + x1.y * wa1.y + x1.z * wa1.z + x1.w * wa1.w;
        #pragma unroll
        for (int sh = 16; sh; sh >>= 1) d += __shfl_xor_sync(0xFFFFFFFFu, d, sh);
        float r = d + g_qatt[g];
        r = r > 0.f ? r : 0.2f * r;                       // LeakyReLU(0.2)
        if (__ldg(sel + e) == 0) r += FRONTIER_BONUS;     // candidate == frontier
        if (l == 0) g_att[e] = r;
        rmax = fmaxf(rmax, r);
        rcnt++;
    }
    if (cur >= 0) {
        float* Sp = &g_S[cur * H];
        atomicAdd(Sp + 4 * l + 0, a0.x);
        atomicAdd(Sp + 4 * l + 1, a0.y);
        atomicAdd(Sp + 4 * l + 2, a0.z);
        atomicAdd(Sp + 4 * l + 3, a0.w);
        atomicAdd(Sp + 128 + 4 * l + 0, a1.x);
        atomicAdd(Sp + 128 + 4 * l + 1, a1.y);
        atomicAdd(Sp + 128 + 4 * l + 2, a1.z);
        atomicAdd(Sp + 128 + 4 * l + 3, a1.w);
        if (l == 0) {
            atomicMax(&g_maxenc[cur], f2o(rmax));
            atomicAdd(&g_cnt[cur], rcnt);
        }
    }
}

// ---------------- segment sum of exp(att - max) over candidate edges ----------------
__global__ void expsum_k(const int* __restrict__ batch,
                         const int* __restrict__ sel, int E) {
    const int RUN = 32;
    int t = blockIdx.x * blockDim.x + threadIdx.x;
    int lo = t * RUN;
    if (lo >= E) return;
    int hi = min(E, lo + RUN);
    int cur = -1;
    float s = 0.f, m = 0.f;
    for (int e = lo; e < hi; e++) {
        int g = batch[e];
        if (g != cur) {
            if (cur >= 0) atomicAdd(&g_sumexp[cur], s);
            s = 0.f; cur = g;
            m = o2f(g_maxenc[g]);
        }
        if (sel[e] == 0) s += expf(g_att[e] - m);
    }
    if (cur >= 0) atomicAdd(&g_sumexp[cur], s);
}

// ---------------- edge_logits ----------------
__global__ void logits_k(const int* __restrict__ batch,
                         const int* __restrict__ sel,
                         float* __restrict__ out, int E) {
    int e = blockIdx.x * blockDim.x + threadIdx.x;
    if (e >= E) return;
    int g = batch[e];
    float p = 0.f;
    if (sel[e] == 0) {
        float m = o2f(g_maxenc[g]);
        p = expf(g_att[e] - m) / fmaxf(g_sumexp[g], F32_EPS);
    }
    out[e] = logf(fmaxf(p, F32_EPS));
}

// ---------------- per-graph: pooled = (S @ W_edge.T)/denom, LN, MLP, stop logit ----------------
__device__ __forceinline__ float block_sum(float v, float* red) {
    int l = threadIdx.x & 31, w = threadIdx.x >> 5;
    #pragma unroll
    for (int sh = 16; sh; sh >>= 1) v += __shfl_xor_sync(0xFFFFFFFFu, v, sh);
    if (l == 0) red[w] = v;
    __syncthreads();
    if (w == 0) {
        float x = (l < 8) ? red[l] : 0.f;
        #pragma unroll
        for (int sh = 4; sh; sh >>= 1) x += __shfl_xor_sync(0xFFFFFFFFu, x, sh);
        if (l == 0) red[0] = x;
    }
    __syncthreads();
    float r = red[0];
    __syncthreads();
    return r;
}

__global__ void __launch_bounds__(256) stop_head_k(
        const float* __restrict__ qtok,
        const float* __restrict__ W_edge,
        const float* __restrict__ ln_g, const float* __restrict__ ln_b,
        const float* __restrict__ W1, const float* __restrict__ b1,
        const float* __restrict__ W2, const float* __restrict__ b2,
        float* __restrict__ out_stop, float* __restrict__ out_pooled) {
    __shared__ float xsh[2 * H];
    __shared__ float ssh[H];
    __shared__ float red[32];
    int g = blockIdx.x, t = threadIdx.x;

    // stage S[g] in shared for the tiny matvec S @ W_edge.T
    ssh[t] = g_S[g * H + t];
    __syncthreads();

    float denom = fmaxf((float)g_cnt[g], 1.0f);
    // pooled[g][t] = (S[g] . W_edge[t,:]) / denom
    float acc = 0.f;
    const float4* wr = (const float4*)(W_edge + (size_t)t * H);
    #pragma unroll 8
    for (int j = 0; j < H / 4; j++) {
        float4 w4 = wr[j];
        acc += w4.x * ssh[4 * j] + w4.y * ssh[4 * j + 1]
             + w4.z * ssh[4 * j + 2] + w4.w * ssh[4 * j + 3];
    }
    float pe = acc / denom;
    out_pooled[(size_t)g * H + t] = pe;
    float qv = qtok[(size_t)g * H + t];

    // LayerNorm over 512
    float mu = block_sum(pe + qv, red) * (1.0f / (2 * H));
    float d0 = pe - mu, d1 = qv - mu;
    float var = block_sum(d0 * d0 + d1 * d1, red) * (1.0f / (2 * H));
    float rstd = rsqrtf(var + LN_EPS);
    xsh[t]     = d0 * rstd * ln_g[t]     + ln_b[t];
    xsh[H + t] = d1 * rstd * ln_g[H + t] + ln_b[H + t];
    __syncthreads();

    // h1[t] = gelu(xn . W1[t,:] + b1[t])
    float a1 = b1[t];
    const float4* w1r = (const float4*)(W1 + (size_t)t * (2 * H));
    #pragma unroll 8
    for (int j = 0; j < (2 * H) / 4; j++) {
        float4 w4 = w1r[j];
        a1 += w4.x * xsh[4 * j] + w4.y * xsh[4 * j + 1]
            + w4.z * xsh[4 * j + 2] + w4.w * xsh[4 * j + 3];
    }
    float h1 = 0.5f * a1 * (1.0f + erff(a1 * 0.70710678118654752f));

    float tot = block_sum(h1 * W2[t], red);
    if (t == 0) out_stop[g] = tot + b2[0];
}

// ---------------- launch ----------------
extern "C" void kernel_launch(void* const* d_in, const int* in_sizes, int n_in,
                              void* d_out, int out_size) {
    const float* edge_tokens = (const float*)d_in[0];
    const float* qtok        = (const float*)d_in[1];
    const int*   batch       = (const int*)d_in[2];
    const int*   sel         = (const int*)d_in[3];
    const float* W_edge      = (const float*)d_in[4];
    // d_in[5] = W_query (folded into g_w_q)
    const float* W_query     = (const float*)d_in[5];
    const float* att_vec     = (const float*)d_in[6];
    const float* ln_g        = (const float*)d_in[7];
    const float* ln_b        = (const float*)d_in[8];
    const float* W1          = (const float*)d_in[9];
    const float* b1          = (const float*)d_in[10];
    const float* W2          = (const float*)d_in[11];
    const float* b2          = (const float*)d_in[12];

    int E = in_sizes[0] / H;
    int G = in_sizes[1] / H;

    float* out = (float*)d_out;
    float* out_edge   = out;            // [E]
    float* out_stop   = out + E;        // [G]
    float* out_pooled = out + E + G;    // [G*H]

    init_k<<<256, 256>>>(G);
    prew_k<<<2, H>>>(W_edge, W_query, att_vec);
    qatt_k<<<(G + 7) / 8, 256>>>(qtok, G);
    pass1_k<<<NBLK_P1, 256>>>(edge_tokens, batch, sel, E);
    {
        int threads = (E + 31) / 32;
        expsum_k<<<(threads + 255) / 256, 256>>>(batch, sel, E);
    }
    logits_k<<<(E + 255) / 256, 256>>>(batch, sel, out_edge, E);
    stop_head_k<<<G, 256>>>(qtok, W_edge, ln_g, ln_b, W1, b1, W2, b2,
                            out_stop, out_pooled);
}

// round 3
// speedup vs baseline: 1.8030x; 1.8030x over previous
#include <cuda_runtime.h>
#include <math.h>

#define H 256
#define MAXE 500000
#define MAXG 256
#define FRONTIER_BONUS 0.5f
#define LN_EPS 1e-5f
#define F32_EPS 1.1920929e-07f
#define NBLK_P1 1184

// ---------------- device scratch (no allocation allowed) ----------------
__device__ float g_w_att[H];          // att_vec @ W_edge
__device__ float g_w_q[H];            // att_vec @ W_query
__device__ float g_qatt[MAXG];        // question_tokens[g] . g_w_q
__device__ float g_S[MAXG * H];       // segment sums of edge_tokens
__device__ int   g_maxenc[MAXG];      // orderable-int encoded segment max of att_raw
__device__ int   g_cnt[MAXG];         // edges per graph
__device__ float g_att[MAXE];         // att_raw per edge

// float <-> orderable signed int (monotonic, for atomicMax)
__device__ __forceinline__ int f2o(float f) {
    int i = __float_as_int(f);
    return i >= 0 ? i : (i ^ 0x7FFFFFFF);
}
__device__ __forceinline__ float o2f(int i) {
    return __int_as_float(i >= 0 ? i : (i ^ 0x7FFFFFFF));
}

// ---------------- init: zero all accumulators ----------------
__global__ void init_k(int G) {
    int i = blockIdx.x * blockDim.x + threadIdx.x;
    int n = G * H;
    for (int j = i; j < n; j += gridDim.x * blockDim.x) g_S[j] = 0.f;
    if (i < H) { g_w_att[i] = 0.f; g_w_q[i] = 0.f; }
    if (i < G) {
        g_maxenc[i] = f2o(-INFINITY);
        g_cnt[i] = 0;
    }
}

// ---------------- precompute w_att, w_q (16 blocks, partial + atomic) ------
__global__ void prew_k(const float* __restrict__ W_edge,
                       const float* __restrict__ W_query,
                       const float* __restrict__ att_vec) {
    int j = threadIdx.x;                 // output column
    int m = blockIdx.x >> 3;             // which matrix
    int c = blockIdx.x & 7;              // row chunk (32 rows)
    const float* W = (m == 0) ? W_edge : W_query;
    float s = 0.f;
    int i0 = c * 32;
    #pragma unroll
    for (int i = 0; i < 32; i++) s = fmaf(__ldg(att_vec + i0 + i), __ldg(W + (i0 + i) * H + j), s);
    float* dst = (m == 0) ? g_w_att : g_w_q;
    atomicAdd(dst + j, s);
}

// ---------------- qatt[g] = question_tokens[g] . w_q ----------------
__global__ void qatt_k(const float* __restrict__ qtok, int G) {
    int w = threadIdx.x >> 5, l = threadIdx.x & 31;
    int g = blockIdx.x * 8 + w;
    if (g >= G) return;
    float s = 0.f;
    #pragma unroll
    for (int k = 0; k < 8; k++) {
        int j = l + 32 * k;
        s += qtok[(size_t)g * H + j] * g_w_q[j];
    }
    #pragma unroll
    for (int sh = 16; sh; sh >>= 1) s += __shfl_xor_sync(0xFFFFFFFFu, s, sh);
    if (l == 0) g_qatt[g] = s;
}

// ---------------- main streaming pass over edge_tokens ----------------
// warp-per-edge, unrolled x2 (two edges in flight per warp iteration).
// Sorted edge_batch -> per-warp run accumulation, rare atomic flush.
struct RunState {
    float4 a0, a1;
    float rmax;
    int cur, rcnt;
    float qcur;
};

__device__ __forceinline__ void flush_run(RunState& st, int l) {
    if (st.cur < 0) return;
    float* Sp = &g_S[st.cur * H];
    atomicAdd(Sp + 4 * l + 0, st.a0.x);
    atomicAdd(Sp + 4 * l + 1, st.a0.y);
    atomicAdd(Sp + 4 * l + 2, st.a0.z);
    atomicAdd(Sp + 4 * l + 3, st.a0.w);
    atomicAdd(Sp + 128 + 4 * l + 0, st.a1.x);
    atomicAdd(Sp + 128 + 4 * l + 1, st.a1.y);
    atomicAdd(Sp + 128 + 4 * l + 2, st.a1.z);
    atomicAdd(Sp + 128 + 4 * l + 3, st.a1.w);
    if (l == 0) {
        atomicMax(&g_maxenc[st.cur], f2o(st.rmax));
        atomicAdd(&g_cnt[st.cur], st.rcnt);
    }
}

__device__ __forceinline__ void process_edge(RunState& st, int g, int selv,
                                             float4 x0, float4 x1,
                                             float4 wa0, float4 wa1,
                                             int e, int l) {
    if (g != st.cur) {
        flush_run(st, l);
        st.a0 = make_float4(0.f, 0.f, 0.f, 0.f);
        st.a1 = make_float4(0.f, 0.f, 0.f, 0.f);
        st.rmax = -INFINITY; st.rcnt = 0; st.cur = g;
        st.qcur = g_qatt[g];
    }
    st.a0.x += x0.x; st.a0.y += x0.y; st.a0.z += x0.z; st.a0.w += x0.w;
    st.a1.x += x1.x; st.a1.y += x1.y; st.a1.z += x1.z; st.a1.w += x1.w;
    float d = x0.x * wa0.x + x0.y * wa0.y + x0.z * wa0.z + x0.w * wa0.w
            + x1.x * wa1.x + x1.y * wa1.y + x1.z * wa1.z + x1.w * wa1.w;
    #pragma unroll
    for (int sh = 16; sh; sh >>= 1) d += __shfl_xor_sync(0xFFFFFFFFu, d, sh);
    float r = d + st.qcur;
    r = r > 0.f ? r : 0.2f * r;                       // LeakyReLU(0.2)
    if (selv == 0) r += FRONTIER_BONUS;               // candidate == frontier
    if (l == 0) g_att[e] = r;
    st.rmax = fmaxf(st.rmax, r);
    st.rcnt++;
}

__global__ void __launch_bounds__(256) pass1_k(const float* __restrict__ x,
                        const int* __restrict__ batch,
                        const int* __restrict__ sel,
                        int E) {
    int chunk = (E + NBLK_P1 - 1) / NBLK_P1;
    int lo = blockIdx.x * chunk;
    int hi = min(E, lo + chunk);
    int w = threadIdx.x >> 5, l = threadIdx.x & 31;

    const float4* wav = (const float4*)g_w_att;
    float4 wa0 = wav[l];       // cols 4l..4l+3
    float4 wa1 = wav[32 + l];  // cols 128+4l..128+4l+3

    RunState st;
    st.a0 = make_float4(0.f, 0.f, 0.f, 0.f);
    st.a1 = make_float4(0.f, 0.f, 0.f, 0.f);
    st.cur = -1; st.rcnt = 0; st.rmax = -INFINITY; st.qcur = 0.f;

    int e = lo + w;
    // unrolled x2: both edges' loads issued before either is consumed -> 2x MLP
    for (; e + 8 < hi; e += 16) {
        int eB = e + 8;
        int gA = __ldg(batch + e);
        int gB = __ldg(batch + eB);
        int sA = __ldg(sel + e);
        int sB = __ldg(sel + eB);
        const float4* rA = (const float4*)(x + (size_t)e * H);
        const float4* rB = (const float4*)(x + (size_t)eB * H);
        float4 xa0 = rA[l];
        float4 xa1 = rA[32 + l];
        float4 xb0 = rB[l];
        float4 xb1 = rB[32 + l];
        process_edge(st, gA, sA, xa0, xa1, wa0, wa1, e, l);
        process_edge(st, gB, sB, xb0, xb1, wa0, wa1, eB, l);
    }
    if (e < hi) {
        int g = __ldg(batch + e);
        int s = __ldg(sel + e);
        const float4* row = (const float4*)(x + (size_t)e * H);
        float4 x0 = row[l];
        float4 x1 = row[32 + l];
        process_edge(st, g, s, x0, x1, wa0, wa1, e, l);
    }
    flush_run(st, l);
}

// ---------------- fused segment softmax + edge logits (block per graph) ----
__device__ __forceinline__ int lower_bound_batch(const int* batch, int E, int key) {
    int lo = 0, hi = E;
    while (lo < hi) {
        int mid = (lo + hi) >> 1;
        if (__ldg(batch + mid) < key) lo = mid + 1; else hi = mid;
    }
    return lo;
}

__global__ void __launch_bounds__(256) softmax_k(const int* __restrict__ batch,
                          const int* __restrict__ sel,
                          float* __restrict__ out, int E) {
    __shared__ float red[32];
    __shared__ float s_inv;
    int g = blockIdx.x, t = threadIdx.x;
    int l = t & 31, w = t >> 5;

    int lo = lower_bound_batch(batch, E, g);
    int hi = lower_bound_batch(batch, E, g + 1);
    if (lo >= hi) return;

    float m = o2f(g_maxenc[g]);
    float s = 0.f;
    for (int e = lo + t; e < hi; e += 256)
        if (__ldg(sel + e) == 0) s += __expf(__ldg(g_att + e) - m) ;
    // correction: use expf for exact rounding parity with reference
    // (recompute below uses expf too)
    #pragma unroll
    for (int sh = 16; sh; sh >>= 1) s += __shfl_xor_sync(0xFFFFFFFFu, s, sh);
    if (l == 0) red[w] = s;
    __syncthreads();
    if (w == 0) {
        float v = (l < 8) ? red[l] : 0.f;
        #pragma unroll
        for (int sh = 4; sh; sh >>= 1) v += __shfl_xor_sync(0xFFFFFFFFu, v, sh);
        if (l == 0) s_inv = 1.0f / fmaxf(v, F32_EPS);
    }
    __syncthreads();
    float inv = s_inv;

    for (int e = lo + t; e < hi; e += 256) {
        float p = 0.f;
        if (__ldg(sel + e) == 0) p = __expf(__ldg(g_att + e) - m) * inv;
        out[e] = logf(fmaxf(p, F32_EPS));
    }
}

// ---------------- per-graph: pooled = (S @ W_edge.T)/denom, LN, MLP, stop ----
__device__ __forceinline__ float block_sum(float v, float* red) {
    int l = threadIdx.x & 31, w = threadIdx.x >> 5;
    #pragma unroll
    for (int sh = 16; sh; sh >>= 1) v += __shfl_xor_sync(0xFFFFFFFFu, v, sh);
    if (l == 0) red[w] = v;
    __syncthreads();
    if (w == 0) {
        float x = (l < 8) ? red[l] : 0.f;
        #pragma unroll
        for (int sh = 4; sh; sh >>= 1) x += __shfl_xor_sync(0xFFFFFFFFu, x, sh);
        if (l == 0) red[0] = x;
    }
    __syncthreads();
    float r = red[0];
    __syncthreads();
    return r;
}

__global__ void __launch_bounds__(256) stop_head_k(
        const float* __restrict__ qtok,
        const float* __restrict__ W_edge,
        const float* __restrict__ ln_g, const float* __restrict__ ln_b,
        const float* __restrict__ W1, const float* __restrict__ b1,
        const float* __restrict__ W2, const float* __restrict__ b2,
        float* __restrict__ out_stop, float* __restrict__ out_pooled) {
    __shared__ float xsh[2 * H];
    __shared__ float ssh[H];
    __shared__ float red[32];
    int g = blockIdx.x, t = threadIdx.x;

    ssh[t] = g_S[g * H + t];
    __syncthreads();

    float denom = fmaxf((float)g_cnt[g], 1.0f);
    float acc = 0.f;
    const float4* wr = (const float4*)(W_edge + (size_t)t * H);
    #pragma unroll 8
    for (int j = 0; j < H / 4; j++) {
        float4 w4 = wr[j];
        acc += w4.x * ssh[4 * j] + w4.y * ssh[4 * j + 1]
             + w4.z * ssh[4 * j + 2] + w4.w * ssh[4 * j + 3];
    }
    float pe = acc / denom;
    out_pooled[(size_t)g * H + t] = pe;
    float qv = qtok[(size_t)g * H + t];

    float mu = block_sum(pe + qv, red) * (1.0f / (2 * H));
    float d0 = pe - mu, d1 = qv - mu;
    float var = block_sum(d0 * d0 + d1 * d1, red) * (1.0f / (2 * H));
    float rstd = rsqrtf(var + LN_EPS);
    xsh[t]     = d0 * rstd * ln_g[t]     + ln_b[t];
    xsh[H + t] = d1 * rstd * ln_g[H + t] + ln_b[H + t];
    __syncthreads();

    float a1 = b1[t];
    const float4* w1r = (const float4*)(W1 + (size_t)t * (2 * H));
    #pragma unroll 8
    for (int j = 0; j < (2 * H) / 4; j++) {
        float4 w4 = w1r[j];
        a1 += w4.x * xsh[4 * j] + w4.y * xsh[4 * j + 1]
            + w4.z * xsh[4 * j + 2] + w4.w * xsh[4 * j + 3];
    }
    float h1 = 0.5f * a1 * (1.0f + erff(a1 * 0.70710678118654752f));

    float tot = block_sum(h1 * W2[t], red);
    if (t == 0) out_stop[g] = tot + b2[0];
}

// ---------------- launch ----------------
extern "C" void kernel_launch(void* const* d_in, const int* in_sizes, int n_in,
                              void* d_out, int out_size) {
    const float* edge_tokens = (const float*)d_in[0];
    const float* qtok        = (const float*)d_in[1];
    const int*   batch       = (const int*)d_in[2];
    const int*   sel         = (const int*)d_in[3];
    const float* W_edge      = (const float*)d_in[4];
    const float* W_query     = (const float*)d_in[5];
    const float* att_vec     = (const float*)d_in[6];
    const float* ln_g        = (const float*)d_in[7];
    const float* ln_b        = (const float*)d_in[8];
    const float* W1          = (const float*)d_in[9];
    const float* b1          = (const float*)d_in[10];
    const float* W2          = (const float*)d_in[11];
    const float* b2          = (const float*)d_in[12];

    int E = in_sizes[0] / H;
    int G = in_sizes[1] / H;

    float* out = (float*)d_out;
    float* out_edge   = out;            // [E]
    float* out_stop   = out + E;        // [G]
    float* out_pooled = out + E + G;    // [G*H]

    init_k<<<256, 256>>>(G);
    prew_k<<<16, H>>>(W_edge, W_query, att_vec);
    qatt_k<<<(G + 7) / 8, 256>>>(qtok, G);
    pass1_k<<<NBLK_P1, 256>>>(edge_tokens, batch, sel, E);
    softmax_k<<<G, 256>>>(batch, sel, out_edge, E);
    stop_head_k<<<G, 256>>>(qtok, W_edge, ln_g, ln_b, W1, b1, W2, b2,
                            out_stop, out_pooled);
}